// round 10
// baseline (speedup 1.0000x reference)
#include <cuda_runtime.h>
#include <math_constants.h>
#include <cstdint>

// Problem: votes (16,6,6,3,3,32,32,4,4); EM routing, 2 iterations.
// Cluster of 4 CTAs per position; CTA q owns input capsules i in [8q, 8q+8).
// Slab/CTA = 144KB -> 132*4*144KB = 76MB concurrent, L2-resident.
#define NPOS   576
#define KHW    9
#define OO     32
#define KDIM   288            // KH*KW*I
#define PERPOS (KDIM*512)
#define EPSC   1e-7f
#define INVT1  0.0005f        // 0.01*(1-0.95^1)
#define INVT2  0.00142625f    // 0.01*(1-0.95^3)

#define NT     256
#define CL     4

// smem layout (floats): 9464 floats = 37856 B -> 4 CTAs/SM (reg-exact too)
#define OFF_G     0            // 8*272 = 2176  per-warp crv partials (pass-A alias)
#define OFF_G2    2176         // 2176
#define OFF_R1    4352         // 288
#define OFF_A8    4640         // 288
#define OFF_Q2T   4928         // 528  [aa*33+o]
#define OFF_MQ1T  5456         // 528
#define OFF_BASE  5984         // 32
#define OFF_S1    6016         // 8
#define OFF_AV    6024         // 544  [o*17+aa] own-eighth sum R1*V
#define OFF_AV2   6568         // 544
#define OFF_AVF   7112         // 544  combined over 4 ranks
#define OFF_AV2F  7656         // 544
#define OFF_GR    8200         // 128  [w*16+m]
#define OFF_SE    8328         // 16   [r*8+w]
#define OFF_FA    8344         // 544  local e-part crv
#define OFF_FB    8888         // 544  local e-part crv2
#define OFF_FC    9432         // 32   local e-part cr
#define SMEM_FLOATS 9464
#define SMEM_BYTES  (SMEM_FLOATS*4)

extern __shared__ float smem[];

__device__ __forceinline__ uint64_t pk2(float lo, float hi) {
    uint64_t r; asm("mov.b64 %0, {%1, %2};" : "=l"(r) : "f"(lo), "f"(hi)); return r;
}
__device__ __forceinline__ void upk2(uint64_t p, float& lo, float& hi) {
    asm("mov.b64 {%0, %1}, %2;" : "=f"(lo), "=f"(hi) : "l"(p));
}
__device__ __forceinline__ uint64_t mul2(uint64_t a, uint64_t b) {
    uint64_t r; asm("mul.rn.f32x2 %0, %1, %2;" : "=l"(r) : "l"(a), "l"(b)); return r;
}
__device__ __forceinline__ uint64_t add2(uint64_t a, uint64_t b) {
    uint64_t r; asm("add.rn.f32x2 %0, %1, %2;" : "=l"(r) : "l"(a), "l"(b)); return r;
}
__device__ __forceinline__ uint64_t fma2(uint64_t a, uint64_t b, uint64_t c) {
    uint64_t r; asm("fma.rn.f32x2 %0, %1, %2, %3;" : "=l"(r) : "l"(a), "l"(b), "l"(c)); return r;
}
__device__ __forceinline__ void bar_pair(int id) {   // 2-warp named barrier
    asm volatile("bar.sync %0, 64;" :: "r"(id) : "memory");
}
__device__ __forceinline__ uint32_t smem_u32(const void* p) {
    uint32_t r;
    asm("{ .reg .u64 t; cvta.to.shared.u64 t, %1; cvt.u32.u64 %0, t; }"
        : "=r"(r) : "l"(p));
    return r;
}
__device__ __forceinline__ uint32_t mapa_rank(uint32_t addr, uint32_t rank) {
    uint32_t r;
    asm("mapa.shared::cluster.u32 %0, %1, %2;" : "=r"(r) : "r"(addr), "r"(rank));
    return r;
}
__device__ __forceinline__ float ld_dsm(uint32_t addr) {
    float v;
    asm volatile("ld.shared::cluster.f32 %0, [%1];" : "=f"(v) : "r"(addr));
    return v;
}
__device__ __forceinline__ void cluster_sync() {
    asm volatile("barrier.cluster.arrive.aligned;" ::: "memory");
    asm volatile("barrier.cluster.wait.aligned;"   ::: "memory");
}
__device__ __forceinline__ uint32_t ctarank() {
    uint32_t r;
    asm("mov.u32 %0, %%cluster_ctarank;" : "=r"(r));
    return r;
}

__global__ __launch_bounds__(NT, 4) __cluster_dims__(CL, 1, 1)
void em_routing_kernel(const float* __restrict__ votes,
                       const float* __restrict__ activ,
                       const float* __restrict__ beta_a,
                       const float* __restrict__ beta_u,
                       float* __restrict__ out)
{
    float* s_G    = smem + OFF_G;
    float* s_G2   = smem + OFF_G2;
    float* s_R1   = smem + OFF_R1;
    float* s_a8   = smem + OFF_A8;
    float* s_q2T  = smem + OFF_Q2T;
    float* s_mq1T = smem + OFF_MQ1T;
    float* s_base = smem + OFF_BASE;
    float* s_S1   = smem + OFF_S1;
    float* s_av   = smem + OFF_AV;
    float* s_av2  = smem + OFF_AV2;
    float* s_avF  = smem + OFF_AVF;
    float* s_av2F = smem + OFF_AV2F;
    float* s_gr   = smem + OFF_GR;
    float* s_se   = smem + OFF_SE;
    float* s_fA   = smem + OFF_FA;
    float* s_fB   = smem + OFF_FB;
    float* s_fC   = smem + OFF_FC;
    float* s_pA   = s_G;               // pass-A slice partials alias (2048 <= 4352)

    const int t   = threadIdx.x;       // 0..255
    const int q   = (int)ctarank();    // 0..3
    const int q8  = 8 * q;
    const int pos = blockIdx.x >> 2;
    const float* __restrict__ V  = votes + (int64_t)pos * PERPOS;
    const float* __restrict__ Ai = activ + pos * KDIM;

    // ---- prologue: full R1/a8 tables, S1 ----
    for (int k = t; k < KDIM; k += NT) {
        float a = Ai[k];
        s_a8[k] = 0.8f * a;
        s_R1[k] = (0.8f * a + 0.2f) * (1.0f / 32.0f);
    }
    __syncthreads();
    if (t < 32) {
        float s = 0.f;
        #pragma unroll
        for (int k = t; k < KDIM; k += 32) s += s_R1[k];
        #pragma unroll
        for (int off = 16; off; off >>= 1) s += __shfl_xor_sync(0xffffffffu, s, off);
        if (t == 0) s_S1[0] = s;
    }

    // ---- Pass A over own 8 i's: slice sl handles il in [4sl,4sl+4), all j ----
    {
        const int sl = t >> 7;           // 0..1
        const int c0 = (t & 127) * 4;
        const ulonglong2* gv =
            (const ulonglong2*)(V + (size_t)(q8 + 4 * sl) * 512 + c0);
        const float* r1 = s_R1 + q8 + 4 * sl;
        uint64_t av0 = 0, av1 = 0, av20 = 0, av21 = 0;
        #pragma unroll
        for (int j = 0; j < KHW; ++j) {
            #pragma unroll
            for (int ilr = 0; ilr < 4; ++ilr) {
                ulonglong2 v = gv[(j * 32 + ilr) * 128];
                float r = r1[j * 32 + ilr];
                uint64_t r2  = pk2(r, r);
                uint64_t rv0 = mul2(r2, v.x);
                uint64_t rv1 = mul2(r2, v.y);
                av0  = add2(av0, rv0);
                av1  = add2(av1, rv1);
                av20 = fma2(rv0, v.x, av20);
                av21 = fma2(rv1, v.y, av21);
            }
        }
        ulonglong2 st;
        st.x = av0;  st.y = av1;
        *(ulonglong2*)(s_pA + sl * 1024 + c0) = st;
        st.x = av20; st.y = av21;
        *(ulonglong2*)(s_pA + sl * 1024 + 512 + c0) = st;
    }
    __syncthreads();

    // ---- local combine -> per-(o,aa) own partials ----
    #pragma unroll
    for (int co = t; co < 512; co += NT) {
        const float av  = s_pA[co] + s_pA[1024 + co];
        const float av2 = s_pA[512 + co] + s_pA[1536 + co];
        const int idx = (co >> 4) * 17 + (co & 15);
        s_av [idx] = av;
        s_av2[idx] = av2;
    }
    cluster_sync();   // #1: partials visible to peers

    // ---- stats: combine 4 ranks (redundant in all CTAs), build tables ----
    #pragma unroll
    for (int co = t; co < 512; co += NT) {
        const int o   = co >> 4;
        const int aa  = co & 15;
        const int idx = o * 17 + aa;
        float av = 0.f, av2 = 0.f;
        const uint32_t a1 = smem_u32(s_av)  + idx * 4;
        const uint32_t a2 = smem_u32(s_av2) + idx * 4;
        #pragma unroll
        for (int r = 0; r < CL; ++r) {
            av  += ld_dsm(mapa_rank(a1, r));
            av2 += ld_dsm(mapa_rank(a2, r));
        }
        s_avF [idx] = av;
        s_av2F[idx] = av2;
        const float S1    = s_S1[0];
        const float invS1 = 1.0f / (S1 + EPSC);
        const float mu1   = av * invS1;
        const float sig1  = fmaf(mu1 * mu1, S1, fmaf(-2.0f * mu1, av, av2)) * invS1;
        const float i2s1  = 0.5f / sig1;           // 1/(2 sigma^2), no eps (ref)
        const float q1    = mu1 * i2s1;
        s_q2T [aa * 33 + o] = i2s1;
        s_mq1T[aa * 33 + o] = -2.0f * q1;

        float Co   = mu1 * q1;
        float cc0  = __logf(fmaf(2.0f * CUDART_PI_F, sig1, EPSC));
        float cost = (beta_u[o] - 0.5f * __logf(sig1 + EPSC)) * S1;
        #pragma unroll
        for (int off = 8; off; off >>= 1) {
            Co   += __shfl_xor_sync(0xffffffffu, Co,   off);
            cc0  += __shfl_xor_sync(0xffffffffu, cc0,  off);
            cost += __shfl_xor_sync(0xffffffffu, cost, off);
        }
        if (aa == 0) {
            float arg = INVT1 * (beta_a[o] - cost);
            float aj  = 1.0f / (1.0f + __expf(-arg));
            s_base[o] = __logf(aj + EPSC) - cc0 - Co;
        }
    }
    __syncthreads();   // tables ready; orders s_pA reads before s_G reuse

    // ---- Fused E-step + M-step-2 over own 8 i's (from L2) ----
    // 8 warps; warp w = (o-half h = w>>2, ib = w&3); rounds r=0..1, i = q8+ib+4r.
    // Pair {w, w^4} shares i, splits o.
    {
        const int w  = t >> 5;
        const int l  = t & 31;
        const int h  = w >> 2;
        const int ib = w & 3;
        const int m  = l & 15;
        const int ah = l >> 4;
        const int o  = h * 16 + m;
        const int barid = ib + 1;        // 1..4

        uint64_t q2p[4], mqp[4];
        #pragma unroll
        for (int p = 0; p < 4; ++p) {
            const int aa0 = ah * 8 + 2 * p;
            q2p[p] = pk2(s_q2T [aa0 * 33 + o], s_q2T [(aa0 + 1) * 33 + o]);
            mqp[p] = pk2(s_mq1T[aa0 * 33 + o], s_mq1T[(aa0 + 1) * 33 + o]);
        }
        const float base = s_base[o];
        float* Gp  = s_G  + w * 272 + m * 17 + ah * 8;
        float* G2p = s_G2 + w * 272 + m * 17 + ah * 8;

        #pragma unroll
        for (int r = 0; r < 2; ++r) {
            const int i = q8 + ib + 4 * r;
            uint64_t g0 = 0, g1 = 0, g2 = 0, g3 = 0;
            uint64_t e0 = 0, e1 = 0, e2 = 0, e3 = 0;
            float gr = 0.f, se = 0.f;

            #pragma unroll 3
            for (int j = 0; j < KHW; ++j) {
                const ulonglong2* pv = (const ulonglong2*)
                    (V + (size_t)(j * 32 + i) * 512 + o * 16 + ah * 8);
                ulonglong2 va = pv[0];
                ulonglong2 vb = pv[1];
                uint64_t t2 = 0;
                t2 = fma2(va.x, fma2(va.x, q2p[0], mqp[0]), t2);
                t2 = fma2(va.y, fma2(va.y, q2p[1], mqp[1]), t2);
                t2 = fma2(vb.x, fma2(vb.x, q2p[2], mqp[2]), t2);
                t2 = fma2(vb.y, fma2(vb.y, q2p[3], mqp[3]), t2);
                float tlo, thi;
                upk2(t2, tlo, thi);
                float term = tlo + thi;
                term += __shfl_xor_sync(0xffffffffu, term, 16);  // join aa-halves
                float e = __expf(base - term);   // un-normalized; fp32-safe range
                se += e;
                float ep = s_a8[j * 32 + i] * e;
                gr += ep;
                uint64_t ep2 = pk2(ep, ep);
                uint64_t rv;
                rv = mul2(ep2, va.x); g0 = add2(g0, rv); e0 = fma2(rv, va.x, e0);
                rv = mul2(ep2, va.y); g1 = add2(g1, rv); e1 = fma2(rv, va.y, e1);
                rv = mul2(ep2, vb.x); g2 = add2(g2, rv); e2 = fma2(rv, vb.x, e2);
                rv = mul2(ep2, vb.y); g3 = add2(g3, rv); e3 = fma2(rv, vb.y, e3);
            }

            // se over warp (each e counted twice by the two ah lanes)
            #pragma unroll
            for (int off = 16; off; off >>= 1)
                se += __shfl_xor_sync(0xffffffffu, se, off);
            if (l == 0) s_se[r * 8 + w] = se;
            bar_pair(barid);       // only pair {w, w^4}
            const float invs =
                1.0f / (0.5f * (s_se[r * 8 + w] + s_se[r * 8 + (w ^ 4)]));

            float lo, hi;
            if (r == 0) {
                upk2(g0, lo, hi); Gp [0] = invs*lo; Gp [1] = invs*hi;
                upk2(g1, lo, hi); Gp [2] = invs*lo; Gp [3] = invs*hi;
                upk2(g2, lo, hi); Gp [4] = invs*lo; Gp [5] = invs*hi;
                upk2(g3, lo, hi); Gp [6] = invs*lo; Gp [7] = invs*hi;
                upk2(e0, lo, hi); G2p[0] = invs*lo; G2p[1] = invs*hi;
                upk2(e1, lo, hi); G2p[2] = invs*lo; G2p[3] = invs*hi;
                upk2(e2, lo, hi); G2p[4] = invs*lo; G2p[5] = invs*hi;
                upk2(e3, lo, hi); G2p[6] = invs*lo; G2p[7] = invs*hi;
                if (ah == 0) s_gr[w * 16 + m] = invs * gr;
            } else {
                upk2(g0, lo, hi); Gp [0] += invs*lo; Gp [1] += invs*hi;
                upk2(g1, lo, hi); Gp [2] += invs*lo; Gp [3] += invs*hi;
                upk2(g2, lo, hi); Gp [4] += invs*lo; Gp [5] += invs*hi;
                upk2(g3, lo, hi); Gp [6] += invs*lo; Gp [7] += invs*hi;
                upk2(e0, lo, hi); G2p[0] += invs*lo; G2p[1] += invs*hi;
                upk2(e1, lo, hi); G2p[2] += invs*lo; G2p[3] += invs*hi;
                upk2(e2, lo, hi); G2p[4] += invs*lo; G2p[5] += invs*hi;
                upk2(e3, lo, hi); G2p[6] += invs*lo; G2p[7] += invs*hi;
                if (ah == 0) s_gr[w * 16 + m] += invs * gr;
            }
        }
    }
    __syncthreads();

    // ---- local e-part combine per (o,aa) over this CTA's 4 i-warps ----
    #pragma unroll
    for (int co = t; co < 512; co += NT) {
        const int o   = co >> 4;
        const int aa  = co & 15;
        const int h   = o >> 4;
        const int m   = o & 15;
        const int idx = o * 17 + aa;
        float crv = 0.f, crv2 = 0.f, cr = 0.f;
        #pragma unroll
        for (int ib = 0; ib < 4; ++ib) {
            const int w = h * 4 + ib;
            crv  += s_G [w * 272 + m * 17 + aa];
            crv2 += s_G2[w * 272 + m * 17 + aa];
            cr   += s_gr[w * 16 + m];
        }
        s_fA[idx] = crv;
        s_fB[idx] = crv2;
        if (aa == 0) s_fC[o] = cr;
    }
    cluster_sync();   // #2: e-partials visible to peers

    // ---- output: CTA q writes o in [8q, 8q+8) ----
    if (t < 128) {
        const int o   = q8 + (t >> 4);
        const int aa  = t & 15;
        const int idx = o * 17 + aa;
        float crv  = 0.2f * s_avF [idx];
        float crv2 = 0.2f * s_av2F[idx];
        float cr   = 0.2f * s_S1[0];
        const uint32_t aA = smem_u32(s_fA) + idx * 4;
        const uint32_t aB = smem_u32(s_fB) + idx * 4;
        const uint32_t aC = smem_u32(s_fC) + o * 4;
        #pragma unroll
        for (int r = 0; r < CL; ++r) {
            crv  += ld_dsm(mapa_rank(aA, r));
            crv2 += ld_dsm(mapa_rank(aB, r));
            cr   += ld_dsm(mapa_rank(aC, r));
        }
        const float invR = 1.0f / (cr + EPSC);
        const float mu2  = crv * invR;
        out[pos * 512 + o * 16 + aa] = mu2;                        // poses

        const float sig2 = fmaf(mu2 * mu2, cr, fmaf(-2.0f * mu2, crv, crv2)) * invR;
        float cost2 = (beta_u[o] - 0.5f * __logf(sig2 + EPSC)) * cr;
        #pragma unroll
        for (int off = 8; off; off >>= 1)
            cost2 += __shfl_xor_sync(0xffffffffu, cost2, off);
        if (aa == 0) {
            float arg = INVT2 * (beta_a[o] - cost2);
            out[NPOS * 512 + pos * OO + o] = 1.0f / (1.0f + __expf(-arg)); // acts
        }
    }

    cluster_sync();   // #3: peers may still read our smem
}

extern "C" void kernel_launch(void* const* d_in, const int* in_sizes, int n_in,
                              void* d_out, int out_size) {
    const float* votes  = (const float*)d_in[0];
    const float* activ  = (const float*)d_in[1];
    const float* beta_a = (const float*)d_in[2];
    const float* beta_u = (const float*)d_in[3];

    cudaFuncSetAttribute(em_routing_kernel,
                         cudaFuncAttributeMaxDynamicSharedMemorySize,
                         SMEM_BYTES);

    em_routing_kernel<<<NPOS * CL, NT, SMEM_BYTES>>>(
        votes, activ, beta_a, beta_u, (float*)d_out);
}